// round 15
// baseline (speedup 1.0000x reference)
#include <cuda_runtime.h>
#include <cuda_fp16.h>
#include <cstdint>

#define N_NODES 50000
#define N_EDGES 800000
#define D_MODEL 128
#define N_HEADS 8
#define D_HEAD  16
#define BUCKET  64      // max in-degree per node (Poisson(16): P(>=64) ~ 1e-19)

#define H_LD 136   // fp16 elems per row of 32-row tiles (272 B: aligned, 4-bank skew)
#define W_LD 392   // fp16 elems per row of qkv W chunk (784 B)

// ---------------- scratch (static device globals; no allocation) -------------
__device__ __align__(16) float  d_q[N_NODES * D_MODEL];
__device__ __align__(16) __half d_kvh[N_NODES * 2 * D_MODEL]; // interleaved k|v per 4-dim group
__device__ __align__(16) __half d_aggh[N_NODES * D_MODEL];
__device__ __align__(16) __half d_wh[D_MODEL * 384];          // qkv_w in fp16
__device__ __align__(16) __half d_owh[D_MODEL * D_MODEL];     // out_w in fp16
__device__ int  d_cnt[N_NODES];
__device__ int2 d_csr[N_NODES * BUCKET];   // {src, edge_id} buckets per dst
__device__ int  d_idx_is64;

// ---------------- kernel 1: fused prep ---------------------------------------
__global__ void prep_kernel(const float* __restrict__ qkv_w,
                            const float* __restrict__ out_w,
                            const int* __restrict__ eiw) {
    const int i = blockIdx.x * blockDim.x + threadIdx.x;   // 0..65535
    if (i == 0) {
        int all_zero = 1;
        #pragma unroll
        for (int j = 0; j < 64; j++)
            if (eiw[2 * j + 1] != 0) all_zero = 0;
        d_idx_is64 = all_zero;
    }
    if (i < N_NODES) d_cnt[i] = 0;
    if (i < D_MODEL * 384) d_wh[i] = __float2half(qkv_w[i]);
    if (i < D_MODEL * D_MODEL) d_owh[i] = __float2half(out_w[i]);
}

// ---------------- kernel 2: scatter edges into fixed-capacity buckets ---------
__global__ void scatter_kernel(const void* __restrict__ ei) {
    const int e = blockIdx.x * blockDim.x + threadIdx.x;
    if (e >= N_EDGES) return;
    int src, dst;
    if (d_idx_is64) {
        src = (int)((const long long*)ei)[e];
        dst = (int)((const long long*)ei)[N_EDGES + e];
    } else {
        src = ((const int*)ei)[e];
        dst = ((const int*)ei)[N_EDGES + e];
    }
    const int pos = atomicAdd(&d_cnt[dst], 1);
    if (pos < BUCKET)
        d_csr[dst * BUCKET + pos] = make_int2(src, e);
}

// ---------------- kernel 3: fused layernorm + QKV GEMM (HMMA) -----------------
__global__ __launch_bounds__(256) void ln_qkv_kernel(
    const float* __restrict__ x,
    const float* __restrict__ qkv_b,   // [384]
    const float* __restrict__ ln_g,    // [128]
    const float* __restrict__ ln_b)    // [128]
{
    __shared__ __align__(16) __half sh_h[32 * H_LD];   // 8.5 KB
    __shared__ __align__(16) __half sh_w[32 * W_LD];   // 24.5 KB

    const int tid   = threadIdx.x;
    const int warp  = tid >> 5;
    const int lane  = tid & 31;
    const int row0  = blockIdx.x * 32;
    const int mtile = warp & 1;
    const int nquad = warp >> 1;

    #pragma unroll
    for (int r = 0; r < 4; r++) {
        const int rr  = warp * 4 + r;
        const int row = min(row0 + rr, N_NODES - 1);
        float4 xv = reinterpret_cast<const float4*>(x)[row * 32 + lane];
        float sum = xv.x + xv.y + xv.z + xv.w;
        float sq  = xv.x * xv.x + xv.y * xv.y + xv.z * xv.z + xv.w * xv.w;
        #pragma unroll
        for (int o = 16; o > 0; o >>= 1) {
            sum += __shfl_xor_sync(0xffffffffu, sum, o);
            sq  += __shfl_xor_sync(0xffffffffu, sq, o);
        }
        const float mean = sum * (1.0f / 128.0f);
        const float var  = sq * (1.0f / 128.0f) - mean * mean;
        const float rstd = rsqrtf(var + 1e-5f);
        float4 gv = reinterpret_cast<const float4*>(ln_g)[lane];
        float4 bv = reinterpret_cast<const float4*>(ln_b)[lane];
        const __half2 h01 = __floats2half2_rn((xv.x - mean) * rstd * gv.x + bv.x,
                                              (xv.y - mean) * rstd * gv.y + bv.y);
        const __half2 h23 = __floats2half2_rn((xv.z - mean) * rstd * gv.z + bv.z,
                                              (xv.w - mean) * rstd * gv.w + bv.w);
        uint2 u;
        u.x = *reinterpret_cast<const unsigned*>(&h01);
        u.y = *reinterpret_cast<const unsigned*>(&h23);
        *reinterpret_cast<uint2*>(&sh_h[rr * H_LD + lane * 4]) = u;
    }

    float acc[12][4];
    #pragma unroll
    for (int t = 0; t < 12; t++)
        #pragma unroll
        for (int j = 0; j < 4; j++) acc[t][j] = 0.0f;

    for (int kc = 0; kc < 4; kc++) {
        __syncthreads();
        #pragma unroll
        for (int j = 0; j < 6; j++) {
            const int i  = tid + j * 256;
            const int kk = i / 48;
            const int cc = i % 48;
            *reinterpret_cast<uint4*>(&sh_w[kk * W_LD + cc * 8]) =
                *reinterpret_cast<const uint4*>(&d_wh[(kc * 32 + kk) * 384 + cc * 8]);
        }
        __syncthreads();

        #pragma unroll
        for (int ks = 0; ks < 2; ks++) {
            unsigned a0, a1, a2, a3;
            {
                const __half* ap = &sh_h[(mtile * 16 + (lane & 15)) * H_LD
                                         + kc * 32 + ks * 16 + (lane >> 4) * 8];
                const unsigned addr = (unsigned)__cvta_generic_to_shared(ap);
                asm volatile(
                    "ldmatrix.sync.aligned.m8n8.x4.shared.b16 {%0,%1,%2,%3}, [%4];"
                    : "=r"(a0), "=r"(a1), "=r"(a2), "=r"(a3) : "r"(addr));
            }
            #pragma unroll
            for (int t = 0; t < 12; t++) {
                const int n_base = nquad * 96 + t * 8;
                unsigned b0, b1;
                {
                    const __half* bp = &sh_w[(ks * 16 + (lane & 15)) * W_LD + n_base];
                    const unsigned addr = (unsigned)__cvta_generic_to_shared(bp);
                    asm volatile(
                        "ldmatrix.sync.aligned.m8n8.x2.trans.shared.b16 {%0,%1}, [%2];"
                        : "=r"(b0), "=r"(b1) : "r"(addr));
                }
                asm volatile(
                    "mma.sync.aligned.m16n8k16.row.col.f32.f16.f16.f32 "
                    "{%0,%1,%2,%3}, {%4,%5,%6,%7}, {%8,%9}, {%0,%1,%2,%3};"
                    : "+f"(acc[t][0]), "+f"(acc[t][1]), "+f"(acc[t][2]), "+f"(acc[t][3])
                    : "r"(a0), "r"(a1), "r"(a2), "r"(a3), "r"(b0), "r"(b1));
            }
        }
    }

    const int rlo = row0 + mtile * 16 + (lane >> 2);
    const int rhi = rlo + 8;
    #pragma unroll
    for (int t = 0; t < 12; t++) {
        const int col = nquad * 96 + t * 8 + 2 * (lane & 3);
        const float b0 = __ldg(qkv_b + col);
        const float b1 = __ldg(qkv_b + col + 1);
        const float d0 = acc[t][0] + b0, d1 = acc[t][1] + b1;
        const float d2 = acc[t][2] + b0, d3 = acc[t][3] + b1;
        if (col < 128) {
            if (rlo < N_NODES) *reinterpret_cast<float2*>(d_q + rlo * 128 + col) = make_float2(d0, d1);
            if (rhi < N_NODES) *reinterpret_cast<float2*>(d_q + rhi * 128 + col) = make_float2(d2, d3);
        } else {
            const int c   = (col < 256) ? col - 128 : col - 256;
            const int off = (c >> 2) * 8 + (c & 3) + ((col < 256) ? 0 : 4);
            if (rlo < N_NODES)
                *reinterpret_cast<__half2*>(d_kvh + rlo * 256 + off) = __floats2half2_rn(d0, d1);
            if (rhi < N_NODES)
                *reinterpret_cast<__half2*>(d_kvh + rhi * 256 + off) = __floats2half2_rn(d2, d3);
        }
    }
}

// ---------------- kernel 4: per-node attention aggregate (4-way MLP) ----------
// One warp per destination node; lane l handles dims [4l,4l+4), head l>>2.
// 4 edges per iteration, all 8 gathers front-batched for DRAM latency cover.
__global__ __launch_bounds__(256) void node_attn_kernel(
    const float* __restrict__ edge_attr)
{
    const int n = blockIdx.x * 8 + (threadIdx.x >> 5);
    if (n >= N_NODES) return;
    const int lane = threadIdx.x & 31;
    const int beg = n * BUCKET;
    const int end = beg + min(d_cnt[n], BUCKET);

    const uint4*  __restrict__ kvp = reinterpret_cast<const uint4*>(d_kvh);
    const float4* __restrict__ ap  = reinterpret_cast<const float4*>(edge_attr);

    const float4 qv = reinterpret_cast<const float4*>(d_q)[n * 32 + lane];
    float4 acc = {0.f, 0.f, 0.f, 0.f};
    float  s   = 0.f;

    int i = beg;
    for (; i + 4 <= end; i += 4) {
        const int2 c0 = d_csr[i];
        const int2 c1 = d_csr[i + 1];
        const int2 c2 = d_csr[i + 2];
        const int2 c3 = d_csr[i + 3];

        // front-batch all 8 gathers (MLP ~8)
        const uint4  kv0 = __ldg(kvp + c0.x * 32 + lane);
        const uint4  kv1 = __ldg(kvp + c1.x * 32 + lane);
        const uint4  kv2 = __ldg(kvp + c2.x * 32 + lane);
        const uint4  kv3 = __ldg(kvp + c3.x * 32 + lane);
        const float4 a0  = __ldg(ap  + c0.y * 32 + lane);
        const float4 a1  = __ldg(ap  + c1.y * 32 + lane);
        const float4 a2  = __ldg(ap  + c2.y * 32 + lane);
        const float4 a3  = __ldg(ap  + c3.y * 32 + lane);

        const float2 k0a = __half22float2(*reinterpret_cast<const __half2*>(&kv0.x));
        const float2 k0b = __half22float2(*reinterpret_cast<const __half2*>(&kv0.y));
        const float2 k1a = __half22float2(*reinterpret_cast<const __half2*>(&kv1.x));
        const float2 k1b = __half22float2(*reinterpret_cast<const __half2*>(&kv1.y));
        const float2 k2a = __half22float2(*reinterpret_cast<const __half2*>(&kv2.x));
        const float2 k2b = __half22float2(*reinterpret_cast<const __half2*>(&kv2.y));
        const float2 k3a = __half22float2(*reinterpret_cast<const __half2*>(&kv3.x));
        const float2 k3b = __half22float2(*reinterpret_cast<const __half2*>(&kv3.y));

        float p0 = qv.x * (k0a.x + a0.x) + qv.y * (k0a.y + a0.y)
                 + qv.z * (k0b.x + a0.z) + qv.w * (k0b.y + a0.w);
        float p1 = qv.x * (k1a.x + a1.x) + qv.y * (k1a.y + a1.y)
                 + qv.z * (k1b.x + a1.z) + qv.w * (k1b.y + a1.w);
        float p2 = qv.x * (k2a.x + a2.x) + qv.y * (k2a.y + a2.y)
                 + qv.z * (k2b.x + a2.z) + qv.w * (k2b.y + a2.w);
        float p3 = qv.x * (k3a.x + a3.x) + qv.y * (k3a.y + a3.y)
                 + qv.z * (k3b.x + a3.z) + qv.w * (k3b.y + a3.w);
        p0 += __shfl_xor_sync(0xffffffffu, p0, 1);
        p1 += __shfl_xor_sync(0xffffffffu, p1, 1);
        p2 += __shfl_xor_sync(0xffffffffu, p2, 1);
        p3 += __shfl_xor_sync(0xffffffffu, p3, 1);
        p0 += __shfl_xor_sync(0xffffffffu, p0, 2);
        p1 += __shfl_xor_sync(0xffffffffu, p1, 2);
        p2 += __shfl_xor_sync(0xffffffffu, p2, 2);
        p3 += __shfl_xor_sync(0xffffffffu, p3, 2);

        const float e0 = __expf(p0 * 0.25f);
        const float e1 = __expf(p1 * 0.25f);
        const float e2 = __expf(p2 * 0.25f);
        const float e3 = __expf(p3 * 0.25f);
        s += (e0 + e1) + (e2 + e3);

        const float2 v0a = __half22float2(*reinterpret_cast<const __half2*>(&kv0.z));
        const float2 v0b = __half22float2(*reinterpret_cast<const __half2*>(&kv0.w));
        const float2 v1a = __half22float2(*reinterpret_cast<const __half2*>(&kv1.z));
        const float2 v1b = __half22float2(*reinterpret_cast<const __half2*>(&kv1.w));
        const float2 v2a = __half22float2(*reinterpret_cast<const __half2*>(&kv2.z));
        const float2 v2b = __half22float2(*reinterpret_cast<const __half2*>(&kv2.w));
        const float2 v3a = __half22float2(*reinterpret_cast<const __half2*>(&kv3.z));
        const float2 v3b = __half22float2(*reinterpret_cast<const __half2*>(&kv3.w));

        acc.x += (e0 * v0a.x + e1 * v1a.x) + (e2 * v2a.x + e3 * v3a.x);
        acc.y += (e0 * v0a.y + e1 * v1a.y) + (e2 * v2a.y + e3 * v3a.y);
        acc.z += (e0 * v0b.x + e1 * v1b.x) + (e2 * v2b.x + e3 * v3b.x);
        acc.w += (e0 * v0b.y + e1 * v1b.y) + (e2 * v2b.y + e3 * v3b.y);
    }
    for (; i < end; i++) {
        const int2 ce = d_csr[i];
        const uint4  kv = __ldg(kvp + ce.x * 32 + lane);
        const float4 av = __ldg(ap  + ce.y * 32 + lane);
        const float2 ka = __half22float2(*reinterpret_cast<const __half2*>(&kv.x));
        const float2 kb = __half22float2(*reinterpret_cast<const __half2*>(&kv.y));
        float p = qv.x * (ka.x + av.x) + qv.y * (ka.y + av.y)
                + qv.z * (kb.x + av.z) + qv.w * (kb.y + av.w);
        p += __shfl_xor_sync(0xffffffffu, p, 1);
        p += __shfl_xor_sync(0xffffffffu, p, 2);
        const float ex = __expf(p * 0.25f);
        s += ex;
        const float2 va = __half22float2(*reinterpret_cast<const __half2*>(&kv.z));
        const float2 vb = __half22float2(*reinterpret_cast<const __half2*>(&kv.w));
        acc.x += ex * va.x; acc.y += ex * va.y;
        acc.z += ex * vb.x; acc.w += ex * vb.y;
    }

    const float inv = 1.0f / fmaxf(s, 1e-16f);
    const __half2 p01 = __floats2half2_rn(acc.x * inv, acc.y * inv);
    const __half2 p23 = __floats2half2_rn(acc.z * inv, acc.w * inv);
    uint2 u;
    u.x = *reinterpret_cast<const unsigned*>(&p01);
    u.y = *reinterpret_cast<const unsigned*>(&p23);
    reinterpret_cast<uint2*>(d_aggh)[n * 32 + lane] = u;
}

// ---------------- kernel 5: output projection + residual (HMMA) ---------------
__global__ __launch_bounds__(256) void out_proj_kernel(
    const float* __restrict__ x,
    const float* __restrict__ out_b,   // [128]
    float* __restrict__ out)
{
    __shared__ __align__(16) __half sh_a[32 * H_LD];        // 8.5 KB
    __shared__ __align__(16) __half sh_w[D_MODEL * H_LD];   // 34 KB

    const int tid   = threadIdx.x;
    const int warp  = tid >> 5;
    const int lane  = tid & 31;
    const int row0  = blockIdx.x * 32;
    const int mtile = warp & 1;
    const int nquad = warp >> 1;

    for (int i = tid; i < 32 * 32; i += 256) {
        const int r   = i >> 5;
        const int g   = i & 31;
        const int row = min(row0 + r, N_NODES - 1);
        *reinterpret_cast<uint2*>(&sh_a[r * H_LD + g * 4]) =
            reinterpret_cast<const uint2*>(d_aggh)[row * 32 + g];
    }
    for (int i = tid; i < D_MODEL * 16; i += 256) {
        const int kk = i >> 4;
        const int cc = i & 15;
        *reinterpret_cast<uint4*>(&sh_w[kk * H_LD + cc * 8]) =
            *reinterpret_cast<const uint4*>(&d_owh[kk * 128 + cc * 8]);
    }
    __syncthreads();

    float acc[4][4];
    #pragma unroll
    for (int t = 0; t < 4; t++)
        #pragma unroll
        for (int j = 0; j < 4; j++) acc[t][j] = 0.0f;

    #pragma unroll
    for (int ks = 0; ks < 8; ks++) {
        unsigned a0, a1, a2, a3;
        {
            const __half* ap = &sh_a[(mtile * 16 + (lane & 15)) * H_LD
                                     + ks * 16 + (lane >> 4) * 8];
            const unsigned addr = (unsigned)__cvta_generic_to_shared(ap);
            asm volatile(
                "ldmatrix.sync.aligned.m8n8.x4.shared.b16 {%0,%1,%2,%3}, [%4];"
                : "=r"(a0), "=r"(a1), "=r"(a2), "=r"(a3) : "r"(addr));
        }
        #pragma unroll
        for (int t = 0; t < 4; t++) {
            const int n_base = nquad * 32 + t * 8;
            unsigned b0, b1;
            {
                const __half* bp = &sh_w[(ks * 16 + (lane & 15)) * H_LD + n_base];
                const unsigned addr = (unsigned)__cvta_generic_to_shared(bp);
                asm volatile(
                    "ldmatrix.sync.aligned.m8n8.x2.trans.shared.b16 {%0,%1}, [%2];"
                    : "=r"(b0), "=r"(b1) : "r"(addr));
            }
            asm volatile(
                "mma.sync.aligned.m16n8k16.row.col.f32.f16.f16.f32 "
                "{%0,%1,%2,%3}, {%4,%5,%6,%7}, {%8,%9}, {%0,%1,%2,%3};"
                : "+f"(acc[t][0]), "+f"(acc[t][1]), "+f"(acc[t][2]), "+f"(acc[t][3])
                : "r"(a0), "r"(a1), "r"(a2), "r"(a3), "r"(b0), "r"(b1));
        }
    }

    const int rlo = row0 + mtile * 16 + (lane >> 2);
    const int rhi = rlo + 8;
    #pragma unroll
    for (int t = 0; t < 4; t++) {
        const int col = nquad * 32 + t * 8 + 2 * (lane & 3);
        const float b0 = __ldg(out_b + col);
        const float b1 = __ldg(out_b + col + 1);
        if (rlo < N_NODES) {
            const float2 xv = *reinterpret_cast<const float2*>(x + rlo * 128 + col);
            *reinterpret_cast<float2*>(out + rlo * 128 + col) =
                make_float2(acc[t][0] + b0 + xv.x, acc[t][1] + b1 + xv.y);
        }
        if (rhi < N_NODES) {
            const float2 xv = *reinterpret_cast<const float2*>(x + rhi * 128 + col);
            *reinterpret_cast<float2*>(out + rhi * 128 + col) =
                make_float2(acc[t][2] + b0 + xv.x, acc[t][3] + b1 + xv.y);
        }
    }
}

// ---------------- launcher ----------------------------------------------------
extern "C" void kernel_launch(void* const* d_in, const int* in_sizes, int n_in,
                              void* d_out, int out_size)
{
    const float* x      = (const float*)d_in[0];
    const float* ea     = (const float*)d_in[1];
    const float* qkv_w  = (const float*)d_in[2];
    const float* qkv_b  = (const float*)d_in[3];
    const float* out_w  = (const float*)d_in[4];
    const float* out_b  = (const float*)d_in[5];
    const float* ln_g   = (const float*)d_in[6];
    const float* ln_b   = (const float*)d_in[7];
    const void*  ei     = d_in[8];
    float*       out    = (float*)d_out;

    const int node_tiles = (N_NODES + 31) / 32;   // 1563

    prep_kernel<<<256, 256>>>(qkv_w, out_w, (const int*)ei);
    scatter_kernel<<<(N_EDGES + 255) / 256, 256>>>(ei);
    ln_qkv_kernel<<<node_tiles, 256>>>(x, qkv_b, ln_g, ln_b);
    node_attn_kernel<<<(N_NODES + 7) / 8, 256>>>(ea);
    out_proj_kernel<<<node_tiles, 256>>>(x, out_b, out);
}